// round 8
// baseline (speedup 1.0000x reference)
#include <cuda_runtime.h>

#define BB 64
#define SS 512
#define HH 1024
#define LL 5

#define NCONS 64            // consumer blocks (crf, one per batch)
#define NPROD 84            // producer blocks (emis)
#define NBLK  (NCONS + NPROD)   // 148 = all resident wave-1
#define TPOS  128           // positions per emis tile
#define NTILES (BB * SS / TPOS) // 256, indexed tile = qtr*64 + batch
#define PCH   64            // h per producer chunk
#define PNCH  (HH / PCH)    // 16
#define PSTRIDE 68          // padded tile row stride (floats)

// Scratch (no allocations allowed).
__device__ float g_emis[BB * SS * LL];
__device__ float g_scores[BB];
__device__ int   g_done = 0;
__device__ int   g_tileFlag[NTILES];

struct ProdShared {
    float sW[LL * HH];               // 20 KB, sW[l*HH + h]
    float sF[2][TPOS * PSTRIDE];     // 2 x 34.8 KB
    float sComb[TPOS * LL];          // 2.5 KB
};
struct ConsShared {
    float4 sXa[SS];                  // exp(e)[0..3]
    float  sXb[SS];                  // exp(e)[4]
    float  sE[(SS + 2) * LL];        // emissions (log), 2 pad rows
    float  sV[SS * LL];              // exact Viterbi values
    float  sMf[64][25];
    float  sLogC[64];
    unsigned sBPw[SS];
    unsigned sPmask[64][5];
    unsigned sEnt[64];
    unsigned char sSel[64];
    float  sRed[256];
    float  sLogZ, sNum;
    int    sFinalTag;
    int    sReady;                   // quarters loaded (0..4)
};
constexpr size_t SMEM_BYTES =
    sizeof(ProdShared) > sizeof(ConsShared) ? sizeof(ProdShared) : sizeof(ConsShared);

__device__ __forceinline__ void cp_async16(void* smem_dst, const void* gsrc) {
    unsigned s = (unsigned)__cvta_generic_to_shared(smem_dst);
    asm volatile("cp.async.cg.shared.global [%0], [%1], 16;\n" :: "r"(s), "l"(gsrc));
}
__device__ __forceinline__ void cp_commit() { asm volatile("cp.async.commit_group;\n"); }
template <int N>
__device__ __forceinline__ void cp_wait() { asm volatile("cp.async.wait_group %0;\n" :: "n"(N)); }

__device__ __forceinline__ float dot4(float4 v, float4 w, float acc) {
    acc = fmaf(v.x, w.x, acc); acc = fmaf(v.y, w.y, acc);
    acc = fmaf(v.z, w.z, acc); acc = fmaf(v.w, w.w, acc);
    return acc;
}
__device__ __forceinline__ void spin_ready(int* p, int n) {
    while (atomicAdd(p, 0) < n) {}
    __threadfence_block();
}

// ---------------------------------------------------------------------------
// Reset kernel: zero tile flags + done counter (graph-replay determinism).
// ---------------------------------------------------------------------------
__global__ void reset_kernel() {
    int i = threadIdx.x;
    if (i < NTILES) g_tileFlag[i] = 0;
    if (i == 0) g_done = 0;
}

// ---------------------------------------------------------------------------
// Fused persistent kernel: 148 blocks x 256 threads.
//   blocks 64..147: producers — stream emis tiles (128 pos), quarter-major
//                   order, flag each tile (fence + atomic release). Producers
//                   NEVER wait on consumers -> progress guaranteed under any
//                   residency.
//   blocks 0..63  : consumers — per-batch CRF racing behind the producers.
// ---------------------------------------------------------------------------
__global__ void __launch_bounds__(256)
fused_kernel(const float* __restrict__ feats,
             const int*   __restrict__ labels,
             const float* __restrict__ W,
             const float* __restrict__ bias,
             const float* __restrict__ start_t,
             const float* __restrict__ end_t,
             const float* __restrict__ trans,
             const float* __restrict__ weights,
             float* __restrict__ out)
{
    __shared__ __align__(16) unsigned char smem_raw[SMEM_BYTES];
    int tid = threadIdx.x, wid = tid >> 5, lane = tid & 31;

    if (blockIdx.x >= NCONS) {
        // =================== PRODUCER ===================
        ProdShared& S = *reinterpret_cast<ProdShared*>(smem_raw);
        int p = blockIdx.x - NCONS;        // 0..83
        int half = tid >> 7;               // h-half of a position
        int posi = tid & 127;              // position within tile

        for (int i = tid; i < HH * LL; i += 256) {
            int h = i / LL, l = i % LL;
            S.sW[l * HH + h] = W[i];
        }
        __syncthreads();

        for (int tile = p; tile < NTILES; tile += NPROD) {
            int q = tile >> 6, b = tile & 63;
            int gbase = b * SS + q * TPOS;         // first position of tile
            const float* fbase = feats + (size_t)gbase * HH;

            auto stage = [&](int k, int bf) {
#pragma unroll
                for (int j = 0; j < 8; j++) {
                    int flat = j * 256 + tid;      // 0..2047
                    int r = flat >> 4, c = flat & 15;
                    cp_async16(&S.sF[bf][r * PSTRIDE + c * 4],
                               fbase + (size_t)r * HH + k * PCH + c * 4);
                }
                cp_commit();
            };

            stage(0, 0);
            float a0 = 0.f, a1 = 0.f, a2 = 0.f, a3 = 0.f, a4 = 0.f;
            int buf = 0;
#pragma unroll 1
            for (int k = 0; k < PNCH; k++) {
                if (k + 1 < PNCH) { stage(k + 1, buf ^ 1); cp_wait<1>(); }
                else              { cp_wait<0>(); }
                __syncthreads();
                const float* frow = &S.sF[buf][posi * PSTRIDE + half * 32];
                const float* w0 = &S.sW[0 * HH + k * PCH + half * 32];
                const float* w1 = &S.sW[1 * HH + k * PCH + half * 32];
                const float* w2 = &S.sW[2 * HH + k * PCH + half * 32];
                const float* w3 = &S.sW[3 * HH + k * PCH + half * 32];
                const float* w4 = &S.sW[4 * HH + k * PCH + half * 32];
#pragma unroll
                for (int i = 0; i < 8; i++) {
                    float4 f = *(const float4*)(frow + i * 4);
                    a0 = dot4(f, *(const float4*)(w0 + i * 4), a0);
                    a1 = dot4(f, *(const float4*)(w1 + i * 4), a1);
                    a2 = dot4(f, *(const float4*)(w2 + i * 4), a2);
                    a3 = dot4(f, *(const float4*)(w3 + i * 4), a3);
                    a4 = dot4(f, *(const float4*)(w4 + i * 4), a4);
                }
                __syncthreads();
                buf ^= 1;
            }
            if (half == 1) {
                S.sComb[posi * LL + 0] = a0; S.sComb[posi * LL + 1] = a1;
                S.sComb[posi * LL + 2] = a2; S.sComb[posi * LL + 3] = a3;
                S.sComb[posi * LL + 4] = a4;
            }
            __syncthreads();
            if (half == 0) {
                float* dst = g_emis + (size_t)(gbase + posi) * LL;
                dst[0] = fmaxf(a0 + S.sComb[posi * LL + 0] + bias[0], 0.f);
                dst[1] = fmaxf(a1 + S.sComb[posi * LL + 1] + bias[1], 0.f);
                dst[2] = fmaxf(a2 + S.sComb[posi * LL + 2] + bias[2], 0.f);
                dst[3] = fmaxf(a3 + S.sComb[posi * LL + 3] + bias[3], 0.f);
                dst[4] = fmaxf(a4 + S.sComb[posi * LL + 4] + bias[4], 0.f);
            }
            __threadfence();            // release: make emis visible device-wide
            __syncthreads();
            if (tid == 0) atomicExch(&g_tileFlag[tile], 1);
            __syncthreads();            // protect sComb/sF before next tile
        }
        return;
    }

    // =================== CONSUMER (CRF for batch b) ===================
    ConsShared& C = *reinterpret_cast<ConsShared*>(smem_raw);
    int b = blockIdx.x;
    if (tid == 0) C.sReady = 0;
    __syncthreads();

    if (wid == 1) {
        // ---- loader warp: pull quarters as producers flag them ----
        for (int q = 0; q < 4; q++) {
            if (lane == 0) {
                while (atomicAdd(&g_tileFlag[q * 64 + b], 0) == 0) __nanosleep(64);
            }
            __syncwarp();
            __threadfence();   // acquire
            size_t base = (size_t)(b * SS + q * TPOS) * LL;
            int ebase = q * TPOS * LL;
            for (int i = lane; i < TPOS * LL; i += 32) {
                float v = g_emis[base + i];
                C.sE[ebase + i] = v;
                float x = __expf(v);
                int t = q * TPOS + i / LL, j = i % LL;
                if (j < 4) ((float*)C.sXa)[t * 4 + j] = x; else C.sXb[t] = x;
            }
            if (q == 3 && lane < 2 * LL) C.sE[SS * LL + lane] = 0.f;  // pad
            __syncwarp();
            __threadfence_block();
            if (lane == 0) atomicExch(&C.sReady, q + 1);
        }
    } else if (wid == 0) {
        // ---- Viterbi value chain (bitwise-exact), quarter-gated ----
        int j = (lane < LL) ? lane : 0;
        float T0 = trans[0 * LL + j], T1 = trans[1 * LL + j], T2 = trans[2 * LL + j],
              T3 = trans[3 * LL + j], T4 = trans[4 * LL + j];
        spin_ready(&C.sReady, 1);
        float v = start_t[j] + C.sE[j];
        if (lane < LL) C.sV[lane] = v;
        int t = 1;
        for (int q = 0; q < 4; q++) {
            if (q > 0) spin_ready(&C.sReady, q + 1);
            float eA = C.sE[t * LL + j];
            float eB = C.sE[(t + 1) * LL + j];
            int tend = q * TPOS + TPOS;
#pragma unroll 4
            for (; t < tend; t++) {
                float v0 = __shfl_sync(0xffffffffu, v, 0);
                float v1 = __shfl_sync(0xffffffffu, v, 1);
                float v2 = __shfl_sync(0xffffffffu, v, 2);
                float v3 = __shfl_sync(0xffffffffu, v, 3);
                float v4 = __shfl_sync(0xffffffffu, v, 4);
                float s0 = v0 + T0, s1 = v1 + T1, s2 = v2 + T2, s3 = v3 + T3, s4 = v4 + T4;
                float m = fmaxf(fmaxf(fmaxf(s0, s1), fmaxf(s2, s3)), s4);
                v = m + eA;  // identical op order to reference
                if (lane < LL) C.sV[t * LL + lane] = v;
                eA = eB;
                eB = C.sE[(t + 2) * LL + j];  // may read ahead; re-read per quarter
            }
        }
        if (lane == 0) {
            float best = C.sV[511 * LL + 0] + end_t[0]; int tag = 0;
#pragma unroll
            for (int i = 1; i < LL; i++) {
                float f = C.sV[511 * LL + i] + end_t[i];
                if (f > best) { best = f; tag = i; }
            }
            C.sFinalTag = tag;
        }
    } else if (wid == 2 || wid == 3) {
        // ---- forward: chunk-parallel (+,*) matrix products ----
        int c = tid - 64;                       // 0..63
        int sc = 1 + 8 * c, ec = min(sc + 8, SS);   // FIX: clamp (c=63 has 7 steps)
        int lastT = ec - 1;                         // last emission index used
        spin_ready(&C.sReady, (lastT >> 7) + 1);    // FIX: target <= 4 always
        float E[LL][LL];
#pragma unroll
        for (int i = 0; i < LL; i++)
#pragma unroll
            for (int jj = 0; jj < LL; jj++) E[i][jj] = __expf(trans[i * LL + jj]);
        float R[LL][LL];
        {
            float4 xa = C.sXa[sc]; float x4[5] = {xa.x, xa.y, xa.z, xa.w, C.sXb[sc]};
#pragma unroll
            for (int i = 0; i < LL; i++)
#pragma unroll
                for (int jj = 0; jj < LL; jj++) R[i][jj] = E[i][jj] * x4[jj];
        }
        for (int t2 = sc + 1; t2 < ec; t2++) {
            float4 xa = C.sXa[t2]; float x4[5] = {xa.x, xa.y, xa.z, xa.w, C.sXb[t2]};
            float Rn[LL][LL];
#pragma unroll
            for (int i = 0; i < LL; i++)
#pragma unroll
                for (int jj = 0; jj < LL; jj++) {
                    float s = fmaf(R[i][0], E[0][jj], R[i][1] * E[1][jj])
                            + fmaf(R[i][2], E[2][jj], R[i][3] * E[3][jj])
                            + R[i][4] * E[4][jj];
                    Rn[i][jj] = s * x4[jj];
                }
#pragma unroll
            for (int i = 0; i < LL; i++)
#pragma unroll
                for (int jj = 0; jj < LL; jj++) R[i][jj] = Rn[i][jj];
        }
        float m = R[0][0];
#pragma unroll
        for (int i = 0; i < LL; i++)
#pragma unroll
            for (int jj = 0; jj < LL; jj++) m = fmaxf(m, R[i][jj]);
        float inv = __fdividef(1.0f, m);
#pragma unroll
        for (int i = 0; i < LL; i++)
#pragma unroll
            for (int jj = 0; jj < LL; jj++) C.sMf[c][i * LL + jj] = R[i][jj] * inv;
        C.sLogC[c] = __logf(m);

        asm volatile("bar.sync 3, 64;" ::: "memory");  // warps 2,3 only

        if (c == 0) {
            float4 xa0 = C.sXa[0];
            float P[5] = {__expf(start_t[0]) * xa0.x, __expf(start_t[1]) * xa0.y,
                          __expf(start_t[2]) * xa0.z, __expf(start_t[3]) * xa0.w,
                          __expf(start_t[4]) * C.sXb[0]};
            float acc = 0.f;
            for (int cc = 0; cc < 64; cc++) {
                const float* M = C.sMf[cc];
                float Pn[5];
#pragma unroll
                for (int jj = 0; jj < LL; jj++)
                    Pn[jj] = fmaf(P[0], M[0 * LL + jj], P[1] * M[1 * LL + jj])
                           + fmaf(P[2], M[2 * LL + jj], P[3] * M[3 * LL + jj])
                           + P[4] * M[4 * LL + jj];
                float s = ((Pn[0] + Pn[1]) + (Pn[2] + Pn[3])) + Pn[4];
                float is = __fdividef(1.0f, s);
                acc += __logf(s) + C.sLogC[cc];
#pragma unroll
                for (int jj = 0; jj < LL; jj++) P[jj] = Pn[jj] * is;
            }
            float z = P[0] * __expf(end_t[0]) + P[1] * __expf(end_t[1])
                    + P[2] * __expf(end_t[2]) + P[3] * __expf(end_t[3])
                    + P[4] * __expf(end_t[4]);
            C.sLogZ = acc + __logf(z);
        }
    } else {
        // ---- numerator (gold path score) partials ----
        spin_ready(&C.sReady, 4);
        const int* lab = labels + b * SS;
        float part = 0.f;
        for (int t2 = tid - 128; t2 < SS; t2 += 128) {
            int l = lab[t2];
            float cc = weights[l] * C.sE[t2 * LL + l];
            if (t2 > 0)       cc += trans[lab[t2 - 1] * LL + l];
            if (t2 == 0)      cc += start_t[l];
            if (t2 == SS - 1) cc += end_t[l];
            part += cc;
        }
        C.sRed[tid] = part;
    }
    __syncthreads();

    // ---- Phase B1: ALL backpointer words in parallel over t (exact replay)
    {
        float Tr[25];
#pragma unroll
        for (int i = 0; i < 25; i++) Tr[i] = trans[i];
        for (int t2 = 1 + tid; t2 < SS; t2 += 256) {
            float a0 = C.sV[(t2 - 1) * LL + 0], a1 = C.sV[(t2 - 1) * LL + 1],
                  a2 = C.sV[(t2 - 1) * LL + 2], a3 = C.sV[(t2 - 1) * LL + 3],
                  a4 = C.sV[(t2 - 1) * LL + 4];
            unsigned word = 0;
#pragma unroll
            for (int jj = 0; jj < LL; jj++) {
                float best = a0 + Tr[0 * LL + jj]; int arg = 0;
                float s1 = a1 + Tr[1 * LL + jj]; if (s1 > best) { best = s1; arg = 1; }
                float s2 = a2 + Tr[2 * LL + jj]; if (s2 > best) { best = s2; arg = 2; }
                float s3 = a3 + Tr[3 * LL + jj]; if (s3 > best) { best = s3; arg = 3; }
                float s4 = a4 + Tr[4 * LL + jj]; if (s4 > best) { best = s4; arg = 4; }
                word |= (unsigned)arg << (3 * jj);
            }
            C.sBPw[t2] = word;
        }
    }
    if (wid == 7) {
        float s = C.sRed[128 + lane] + C.sRed[160 + lane]
                + C.sRed[192 + lane] + C.sRed[224 + lane];
#pragma unroll
        for (int off = 16; off > 0; off >>= 1) s += __shfl_xor_sync(0xffffffffu, s, off);
        if (lane == 0) C.sNum = s;
    }
    __syncthreads();

    // ---- Phase B2: per-chunk integer tag-map composition
    if (tid < 64) {
        int c = tid, sc = 1 + 8 * c, ec = min(sc + 8, SS);  // FIX: clamp
        unsigned ent = 0;
#pragma unroll
        for (int g = 0; g < LL; g++) {
            int tag = g;
            unsigned pk = 0;
            for (int t2 = ec - 1; t2 >= sc; t2--) {
                pk |= (unsigned)tag << (3 * (t2 - sc));
                tag = (int)((C.sBPw[t2] >> (3 * tag)) & 7u);
            }
            C.sPmask[c][g] = pk;
            ent |= (unsigned)tag << (3 * g);
        }
        C.sEnt[c] = ent;
    }
    __syncthreads();

    // ---- Phase C: compose integer entry maps
    if (tid == 0) {
        int tag = C.sFinalTag;
#pragma unroll 8
        for (int c = 63; c >= 0; c--) {
            C.sSel[c] = (unsigned char)tag;
            tag = (int)((C.sEnt[c] >> (3 * tag)) & 7u);
        }
        out[1 + b * SS + 0] = (float)tag;  // path[0]
        g_scores[b] = C.sNum - C.sLogZ;
    }
    __syncthreads();

    // ---- Phase D: parallel path emit (bounded: c=63 emits 7)
    if (tid < 64) {
        int c = tid, sc = 1 + 8 * c, ec = min(sc + 8, SS);  // FIX: clamp
        unsigned pk = C.sPmask[c][C.sSel[c]];
        for (int t2 = sc; t2 < ec; t2++)
            out[1 + b * SS + t2] = (float)((pk >> (3 * (t2 - sc))) & 7u);
    }

    // ---- fused finalize: last consumer block reduces loss
    if (tid == 0) {
        __threadfence();
        int old = atomicAdd(&g_done, 1);
        if (old == NCONS - 1) {
            __threadfence();
            float s = 0.f;
#pragma unroll 8
            for (int i = 0; i < BB; i++) s += g_scores[i];
            out[0] = -s / (float)(BB * SS);
        }
    }
}

extern "C" void kernel_launch(void* const* d_in, const int* in_sizes, int n_in,
                              void* d_out, int out_size) {
    const float* feats   = (const float*)d_in[0];  // [B,S,H]
    const int*   labels  = (const int*)  d_in[1];  // [B,S]
    // d_in[2] = mask: constant all-True, folded away
    const float* W_tag   = (const float*)d_in[3];  // [H,L]
    const float* b_tag   = (const float*)d_in[4];  // [L]
    const float* start_t = (const float*)d_in[5];  // [L]
    const float* end_t   = (const float*)d_in[6];  // [L]
    const float* trans   = (const float*)d_in[7];  // [L,L]
    const float* weights = (const float*)d_in[8];  // [L]
    float* out = (float*)d_out;                    // [1 + B*S]: loss, then paths

    reset_kernel<<<1, 256>>>();
    fused_kernel<<<NBLK, 256>>>(feats, labels, W_tag, b_tag,
                                start_t, end_t, trans, weights, out);
}